// round 1
// baseline (speedup 1.0000x reference)
#include <cuda_runtime.h>
#include <cstddef>

typedef unsigned long long ull;

// Packed f32x2 FMA (Blackwell sm_103a): d.lo = a.lo*b.lo + c.lo, same for .hi
__device__ __forceinline__ ull ffma2(ull a, ull b, ull c) {
    ull d;
    asm("fma.rn.f32x2 %0, %1, %2, %3;" : "=l"(d) : "l"(a), "l"(b), "l"(c));
    return d;
}
__device__ __forceinline__ float lo32(ull v) { return __uint_as_float((unsigned)v); }
__device__ __forceinline__ float hi32(ull v) { return __uint_as_float((unsigned)(v >> 32)); }

#define B_    256
#define IN_   2048
#define NC_   1000
#define O_    4096
#define H_    4
#define NDEC  (O_ * H_)   // 16384
#define NEG_SLOPE 0.1f

#define BM 128
#define BN 128
#define BK 16
#define AP 132   // padded As row stride (floats)
#define BP 130   // padded Bs row stride (float2)

#define FSPLIT 8
__device__ float fc_scratch[FSPLIT * B_ * NC_];

// ---------------------------------------------------------------------------
// Decoder kernel: C[256, 16384] = X[256,2048] @ W1r[2048,16384]
// Epilogue: +b1, leaky, collapse h-quads with W2, +b2 -> out2[256,4096]
// ---------------------------------------------------------------------------
__global__ __launch_bounds__(256, 2)
void decoder_kernel(const float* __restrict__ x, const float* __restrict__ W1,
                    const float* __restrict__ b1, const float* __restrict__ W2,
                    const float* __restrict__ b2, float* __restrict__ out2)
{
    __shared__ float  As[BK][AP];   // A tile, transposed [k][m]
    __shared__ float2 Bs[BK][BP];   // B tile, pre-splatted {b,b}

    const int tid = threadIdx.x;          // 256 threads
    const int tx = tid & 15;              // n-group 0..15 (8 cols each)
    const int ty = tid >> 4;              // m-group 0..15 (8 rows each)
    const int m0 = blockIdx.y * BM;
    const int n0 = blockIdx.x * BN;

    ull acc[4][8];                        // m packed in pairs
    #pragma unroll
    for (int i = 0; i < 4; i++)
        #pragma unroll
        for (int j = 0; j < 8; j++) acc[i][j] = 0ull;

    const int ar = tid >> 2;              // A load row 0..63
    const int ac = (tid & 3) * 4;         // A load col (float4)
    const int o_l  = tid >> 3;            // local decoder 0..31
    const int bsub = (tid & 7) * 8;       // 8-float chunk inside 64-float (k,h) block
    const float* w1p = W1 + (size_t)(n0 / 4 + o_l) * (IN_ * H_) + bsub;

    for (int kt = 0; kt < IN_ / BK; kt++) {
        const int k0 = kt * BK;
        // ---- load A tile (128x16), store transposed ----
        #pragma unroll
        for (int p = 0; p < 2; p++) {
            float4 v = *(const float4*)&x[(size_t)(m0 + ar + p * 64) * IN_ + k0 + ac];
            As[ac + 0][ar + p * 64] = v.x;
            As[ac + 1][ar + p * 64] = v.y;
            As[ac + 2][ar + p * 64] = v.z;
            As[ac + 3][ar + p * 64] = v.w;
        }
        // ---- load B tile: per decoder o, 64 contiguous floats (16 k x 4 h) ----
        {
            const float* p0 = w1p + (size_t)k0 * H_;
            float4 v0 = *(const float4*)(p0);
            float4 v1 = *(const float4*)(p0 + 4);
            float vv[8] = {v0.x, v0.y, v0.z, v0.w, v1.x, v1.y, v1.z, v1.w};
            #pragma unroll
            for (int e = 0; e < 8; e++) {
                int idx = bsub + e;                 // 0..63 within (k,h) block
                Bs[idx >> 2][(o_l << 2) + (idx & 3)] = make_float2(vv[e], vv[e]);
            }
        }
        __syncthreads();
        // ---- inner product: pure FFMA2 ----
        #pragma unroll
        for (int k = 0; k < BK; k++) {
            const ull* ap = (const ull*)&As[k][ty * 8];
            const ull* bp = (const ull*)&Bs[k][tx * 8];
            ull a0 = ap[0], a1 = ap[1], a2 = ap[2], a3 = ap[3];
            ull bv[8];
            #pragma unroll
            for (int j = 0; j < 8; j++) bv[j] = bp[j];
            #pragma unroll
            for (int j = 0; j < 8; j++) {
                acc[0][j] = ffma2(a0, bv[j], acc[0][j]);
                acc[1][j] = ffma2(a1, bv[j], acc[1][j]);
                acc[2][j] = ffma2(a2, bv[j], acc[2][j]);
                acc[3][j] = ffma2(a3, bv[j], acc[3][j]);
            }
        }
        __syncthreads();
    }

    // ---- epilogue: bias, leaky relu, collapse h-quads ----
    const int gnb = n0 + tx * 8;          // global n base (2 full decoders)
    float b1v[8], w2v[8];
    #pragma unroll
    for (int j = 0; j < 8; j++) { b1v[j] = b1[gnb + j]; w2v[j] = W2[gnb + j]; }
    const int o_g = gnb >> 2;
    const float b2v0 = b2[o_g], b2v1 = b2[o_g + 1];

    #pragma unroll
    for (int m2 = 0; m2 < 4; m2++) {
        #pragma unroll
        for (int half = 0; half < 2; half++) {
            const int gm = m0 + ty * 8 + m2 * 2 + half;
            float s0 = 0.f, s1 = 0.f;
            #pragma unroll
            for (int h = 0; h < 4; h++) {
                float v0 = half ? hi32(acc[m2][h]) : lo32(acc[m2][h]);
                v0 += b1v[h];
                v0 = v0 >= 0.f ? v0 : NEG_SLOPE * v0;
                s0 += v0 * w2v[h];
                float v1 = half ? hi32(acc[m2][4 + h]) : lo32(acc[m2][4 + h]);
                v1 += b1v[4 + h];
                v1 = v1 >= 0.f ? v1 : NEG_SLOPE * v1;
                s1 += v1 * w2v[4 + h];
            }
            out2[(size_t)gm * O_ + o_g]     = s0 + b2v0;
            out2[(size_t)gm * O_ + o_g + 1] = s1 + b2v1;
        }
    }
}

// ---------------------------------------------------------------------------
// fc head: x1 = x @ fcW^T + fcb, split-K=8 into scratch, then reduce.
// ---------------------------------------------------------------------------
__global__ __launch_bounds__(256, 2)
void fc_kernel(const float* __restrict__ x, const float* __restrict__ fcW)
{
    __shared__ float  As[BK][AP];
    __shared__ float2 Bs[BK][BP];

    const int tid = threadIdx.x;
    const int tx = tid & 15;
    const int ty = tid >> 4;
    const int m0 = blockIdx.y * BM;
    const int n0 = blockIdx.x * BN;
    const int z  = blockIdx.z;

    ull acc[4][8];
    #pragma unroll
    for (int i = 0; i < 4; i++)
        #pragma unroll
        for (int j = 0; j < 8; j++) acc[i][j] = 0ull;

    const int ar = tid >> 2;
    const int ac = (tid & 3) * 4;
    const int n_l = tid >> 1;             // 0..127
    const int c8  = (tid & 1) * 8;        // k sub-chunk
    const int n_g = n0 + n_l;
    const bool nvalid = (n_g < NC_);

    for (int kt = 0; kt < (IN_ / FSPLIT) / BK; kt++) {
        const int k0 = z * (IN_ / FSPLIT) + kt * BK;
        #pragma unroll
        for (int p = 0; p < 2; p++) {
            float4 v = *(const float4*)&x[(size_t)(m0 + ar + p * 64) * IN_ + k0 + ac];
            As[ac + 0][ar + p * 64] = v.x;
            As[ac + 1][ar + p * 64] = v.y;
            As[ac + 2][ar + p * 64] = v.z;
            As[ac + 3][ar + p * 64] = v.w;
        }
        {
            float vv[8] = {0.f, 0.f, 0.f, 0.f, 0.f, 0.f, 0.f, 0.f};
            if (nvalid) {
                float4 v0 = *(const float4*)&fcW[(size_t)n_g * IN_ + k0 + c8];
                float4 v1 = *(const float4*)&fcW[(size_t)n_g * IN_ + k0 + c8 + 4];
                vv[0] = v0.x; vv[1] = v0.y; vv[2] = v0.z; vv[3] = v0.w;
                vv[4] = v1.x; vv[5] = v1.y; vv[6] = v1.z; vv[7] = v1.w;
            }
            #pragma unroll
            for (int e = 0; e < 8; e++)
                Bs[c8 + e][n_l] = make_float2(vv[e], vv[e]);
        }
        __syncthreads();
        #pragma unroll
        for (int k = 0; k < BK; k++) {
            const ull* ap = (const ull*)&As[k][ty * 8];
            const ull* bp = (const ull*)&Bs[k][tx * 8];
            ull a0 = ap[0], a1 = ap[1], a2 = ap[2], a3 = ap[3];
            ull bv[8];
            #pragma unroll
            for (int j = 0; j < 8; j++) bv[j] = bp[j];
            #pragma unroll
            for (int j = 0; j < 8; j++) {
                acc[0][j] = ffma2(a0, bv[j], acc[0][j]);
                acc[1][j] = ffma2(a1, bv[j], acc[1][j]);
                acc[2][j] = ffma2(a2, bv[j], acc[2][j]);
                acc[3][j] = ffma2(a3, bv[j], acc[3][j]);
            }
        }
        __syncthreads();
    }

    float* scr = fc_scratch + (size_t)z * (B_ * NC_);
    #pragma unroll
    for (int m2 = 0; m2 < 4; m2++) {
        #pragma unroll
        for (int half = 0; half < 2; half++) {
            const int gm = m0 + ty * 8 + m2 * 2 + half;
            #pragma unroll
            for (int j = 0; j < 8; j++) {
                const int gn = n0 + tx * 8 + j;
                if (gn < NC_) {
                    float v = half ? hi32(acc[m2][j]) : lo32(acc[m2][j]);
                    scr[(size_t)gm * NC_ + gn] = v;
                }
            }
        }
    }
}

__global__ void fc_reduce(const float* __restrict__ fcb, float* __restrict__ out1)
{
    const int i = blockIdx.x * blockDim.x + threadIdx.x;
    if (i >= B_ * NC_) return;
    const int c = i % NC_;
    float s = fcb[c];
    #pragma unroll
    for (int z = 0; z < FSPLIT; z++) s += fc_scratch[(size_t)z * (B_ * NC_) + i];
    out1[i] = s;
}

// ---------------------------------------------------------------------------
extern "C" void kernel_launch(void* const* d_in, const int* in_sizes, int n_in,
                              void* d_out, int out_size)
{
    const float* x   = (const float*)d_in[0];
    const float* fcW = (const float*)d_in[1];
    const float* fcb = (const float*)d_in[2];
    const float* W1  = (const float*)d_in[3];
    const float* b1  = (const float*)d_in[4];
    const float* W2  = (const float*)d_in[5];
    const float* b2  = (const float*)d_in[6];

    float* out1 = (float*)d_out;            // x1 [256,1000]
    float* out2 = out1 + B_ * NC_;          // x2 [256,4096]

    dim3 gfc((NC_ + BN - 1) / BN, B_ / BM, FSPLIT);   // 8 x 2 x 8 = 128 CTAs
    fc_kernel<<<gfc, 256>>>(x, fcW);
    fc_reduce<<<(B_ * NC_ + 255) / 256, 256>>>(fcb, out1);

    dim3 gdec(NDEC / BN, B_ / BM);                     // 128 x 2 = 256 CTAs
    decoder_kernel<<<gdec, 256>>>(x, W1, b1, W2, b2, out2);
}

// round 2
// speedup vs baseline: 2.3876x; 2.3876x over previous
#include <cuda_runtime.h>
#include <cstddef>

typedef unsigned long long ull;

// Packed f32x2 FMA (Blackwell sm_103a)
__device__ __forceinline__ ull ffma2(ull a, ull b, ull c) {
    ull d;
    asm("fma.rn.f32x2 %0, %1, %2, %3;" : "=l"(d) : "l"(a), "l"(b), "l"(c));
    return d;
}
__device__ __forceinline__ float lo32(ull v) { return __uint_as_float((unsigned)v); }
__device__ __forceinline__ float hi32(ull v) { return __uint_as_float((unsigned)(v >> 32)); }

#define B_    256
#define IN_   2048
#define NC_   1000
#define O_    4096
#define H_    4
#define NDEC  (O_ * H_)   // 16384
#define NEG_SLOPE 0.1f

#define BM 128
#define BN 128
#define BK 16
#define APAD 130   // As2 row stride in float2 (even -> 16B aligned rows)

#define FSPLIT 8
__device__ float fc_scratch[FSPLIT * B_ * NC_];

// ---------------------------------------------------------------------------
// Core fragment compute shared by both GEMMs:
//   As2: splatted A  float2[BK][APAD]   (read = broadcast)
//   Bs : plain B     float [BK][BN]     (read = conflict-free LDS.128)
//   acc[r][j]: r = m row 0..7 (ty*8+r), j = n pair
//      j=0,1 -> n = tx*4 + {0,1},{2,3} ; j=2,3 -> n = 64 + tx*4 + {0,1},{2,3}
// ---------------------------------------------------------------------------
#define INNER_LOOP(As2, Bs, acc, tx, ty)                                      \
    _Pragma("unroll")                                                         \
    for (int k = 0; k < BK; k++) {                                            \
        ull a[8];                                                             \
        _Pragma("unroll")                                                     \
        for (int i = 0; i < 4; i++) {                                         \
            ulonglong2 u = *(const ulonglong2*)&As2[k][ty * 8 + 2 * i];       \
            a[2 * i] = u.x; a[2 * i + 1] = u.y;                               \
        }                                                                     \
        ulonglong2 b0 = *(const ulonglong2*)&Bs[k][tx * 4];                   \
        ulonglong2 b1 = *(const ulonglong2*)&Bs[k][64 + tx * 4];              \
        ull bv[4] = {b0.x, b0.y, b1.x, b1.y};                                 \
        _Pragma("unroll")                                                     \
        for (int r = 0; r < 8; r++) {                                         \
            _Pragma("unroll")                                                 \
            for (int j = 0; j < 4; j++)                                       \
                acc[r][j] = ffma2(a[r], bv[j], acc[r][j]);                    \
        }                                                                     \
    }

// ---------------------------------------------------------------------------
// Decoder: C[256,16384] = X @ W1r, epilogue bias+leaky+collapse -> [256,4096]
// ---------------------------------------------------------------------------
__global__ __launch_bounds__(256, 2)
void decoder_kernel(const float* __restrict__ x, const float* __restrict__ W1,
                    const float* __restrict__ b1, const float* __restrict__ W2,
                    const float* __restrict__ b2, float* __restrict__ out2)
{
    __shared__ float2 As2[BK][APAD];
    __shared__ float  Bs[BK][BN];

    const int tid = threadIdx.x;
    const int tx = tid & 15;
    const int ty = tid >> 4;
    const int m0 = blockIdx.y * BM;
    const int n0 = blockIdx.x * BN;

    ull acc[8][4];
    #pragma unroll
    for (int r = 0; r < 8; r++)
        #pragma unroll
        for (int j = 0; j < 4; j++) acc[r][j] = 0ull;

    // A loaders
    const int ar = tid >> 2;              // 0..63
    const int ac = (tid & 3) * 4;         // k offset (float4)
    // B loaders: decoder o_l = tid&31, chunk e = tid>>5
    const int o_l = tid & 31;
    const int e   = tid >> 5;             // 0..7
    const float* w1p = W1 + (size_t)(n0 / 4 + o_l) * (IN_ * H_) + e * 8;

    for (int kt = 0; kt < IN_ / BK; kt++) {
        const int k0 = kt * BK;
        // A tile -> splatted, transposed
        #pragma unroll
        for (int p = 0; p < 2; p++) {
            float4 v = *(const float4*)&x[(size_t)(m0 + ar + p * 64) * IN_ + k0 + ac];
            As2[ac + 0][ar + p * 64] = make_float2(v.x, v.x);
            As2[ac + 1][ar + p * 64] = make_float2(v.y, v.y);
            As2[ac + 2][ar + p * 64] = make_float2(v.z, v.z);
            As2[ac + 3][ar + p * 64] = make_float2(v.w, v.w);
        }
        // B tile: 32B contiguous per thread from decoder o_l
        {
            const float* p0 = w1p + (size_t)k0 * H_;
            float4 v0 = *(const float4*)(p0);
            float4 v1 = *(const float4*)(p0 + 4);
            *(float4*)&Bs[2 * e][o_l * 4]     = v0;   // k=2e,  h0..3
            *(float4*)&Bs[2 * e + 1][o_l * 4] = v1;   // k=2e+1,h0..3
        }
        __syncthreads();
        INNER_LOOP(As2, Bs, acc, tx, ty)
        __syncthreads();
    }

    // Epilogue: each thread owns decoders d0,d1 (full h-quads)
    const int gn0 = n0 + tx * 4;
    const int gn1 = gn0 + 64;
    const int d0 = gn0 >> 2, d1 = gn1 >> 2;
    float b1a[4], w2a[4], b1b[4], w2b[4];
    #pragma unroll
    for (int h = 0; h < 4; h++) {
        b1a[h] = b1[gn0 + h]; w2a[h] = W2[gn0 + h];
        b1b[h] = b1[gn1 + h]; w2b[h] = W2[gn1 + h];
    }
    const float b2a = b2[d0], b2b = b2[d1];

    #pragma unroll
    for (int r = 0; r < 8; r++) {
        const int gm = m0 + ty * 8 + r;
        float s0 = 0.f, s1 = 0.f;
        #pragma unroll
        for (int j = 0; j < 2; j++) {
            float va0 = lo32(acc[r][j]) + b1a[2 * j];
            float va1 = hi32(acc[r][j]) + b1a[2 * j + 1];
            va0 = va0 >= 0.f ? va0 : NEG_SLOPE * va0;
            va1 = va1 >= 0.f ? va1 : NEG_SLOPE * va1;
            s0 += va0 * w2a[2 * j] + va1 * w2a[2 * j + 1];
            float vb0 = lo32(acc[r][j + 2]) + b1b[2 * j];
            float vb1 = hi32(acc[r][j + 2]) + b1b[2 * j + 1];
            vb0 = vb0 >= 0.f ? vb0 : NEG_SLOPE * vb0;
            vb1 = vb1 >= 0.f ? vb1 : NEG_SLOPE * vb1;
            s1 += vb0 * w2b[2 * j] + vb1 * w2b[2 * j + 1];
        }
        out2[(size_t)gm * O_ + d0] = s0 + b2a;
        out2[(size_t)gm * O_ + d1] = s1 + b2b;
    }
}

// ---------------------------------------------------------------------------
// fc head: split-K=8 into scratch, then reduce.
// ---------------------------------------------------------------------------
__global__ __launch_bounds__(256, 2)
void fc_kernel(const float* __restrict__ x, const float* __restrict__ fcW)
{
    __shared__ float2 As2[BK][APAD];
    __shared__ float  Bs[BK][BN];

    const int tid = threadIdx.x;
    const int tx = tid & 15;
    const int ty = tid >> 4;
    const int m0 = blockIdx.y * BM;
    const int n0 = blockIdx.x * BN;
    const int z  = blockIdx.z;

    ull acc[8][4];
    #pragma unroll
    for (int r = 0; r < 8; r++)
        #pragma unroll
        for (int j = 0; j < 4; j++) acc[r][j] = 0ull;

    const int ar = tid >> 2;
    const int ac = (tid & 3) * 4;
    const int n_l  = tid >> 1;            // 0..127
    const int kc   = (tid & 1) * 8;       // k sub-chunk
    const int n_g  = n0 + n_l;
    const bool nvalid = (n_g < NC_);

    for (int kt = 0; kt < (IN_ / FSPLIT) / BK; kt++) {
        const int k0 = z * (IN_ / FSPLIT) + kt * BK;
        #pragma unroll
        for (int p = 0; p < 2; p++) {
            float4 v = *(const float4*)&x[(size_t)(m0 + ar + p * 64) * IN_ + k0 + ac];
            As2[ac + 0][ar + p * 64] = make_float2(v.x, v.x);
            As2[ac + 1][ar + p * 64] = make_float2(v.y, v.y);
            As2[ac + 2][ar + p * 64] = make_float2(v.z, v.z);
            As2[ac + 3][ar + p * 64] = make_float2(v.w, v.w);
        }
        {
            float vv[8] = {0.f,0.f,0.f,0.f,0.f,0.f,0.f,0.f};
            if (nvalid) {
                float4 v0 = *(const float4*)&fcW[(size_t)n_g * IN_ + k0 + kc];
                float4 v1 = *(const float4*)&fcW[(size_t)n_g * IN_ + k0 + kc + 4];
                vv[0]=v0.x; vv[1]=v0.y; vv[2]=v0.z; vv[3]=v0.w;
                vv[4]=v1.x; vv[5]=v1.y; vv[6]=v1.z; vv[7]=v1.w;
            }
            #pragma unroll
            for (int q = 0; q < 8; q++)
                Bs[kc + q][n_l] = vv[q];
        }
        __syncthreads();
        INNER_LOOP(As2, Bs, acc, tx, ty)
        __syncthreads();
    }

    float* scr = fc_scratch + (size_t)z * (B_ * NC_);
    const int gn0 = n0 + tx * 4;
    #pragma unroll
    for (int r = 0; r < 8; r++) {
        const int gm = m0 + ty * 8 + r;
        #pragma unroll
        for (int j = 0; j < 4; j++) {
            const int gn = gn0 + (j >> 1) * 64 + (j & 1) * 2;
            float v0 = lo32(acc[r][j]);
            float v1 = hi32(acc[r][j]);
            if (gn < NC_)     scr[(size_t)gm * NC_ + gn]     = v0;
            if (gn + 1 < NC_) scr[(size_t)gm * NC_ + gn + 1] = v1;
        }
    }
}

__global__ void fc_reduce(const float* __restrict__ fcb, float* __restrict__ out1)
{
    const int i = blockIdx.x * blockDim.x + threadIdx.x;
    if (i >= B_ * NC_) return;
    const int c = i % NC_;
    float s = fcb[c];
    #pragma unroll
    for (int z = 0; z < FSPLIT; z++) s += fc_scratch[(size_t)z * (B_ * NC_) + i];
    out1[i] = s;
}

// ---------------------------------------------------------------------------
extern "C" void kernel_launch(void* const* d_in, const int* in_sizes, int n_in,
                              void* d_out, int out_size)
{
    const float* x   = (const float*)d_in[0];
    const float* fcW = (const float*)d_in[1];
    const float* fcb = (const float*)d_in[2];
    const float* W1  = (const float*)d_in[3];
    const float* b1  = (const float*)d_in[4];
    const float* W2  = (const float*)d_in[5];
    const float* b2  = (const float*)d_in[6];

    float* out1 = (float*)d_out;            // x1 [256,1000]
    float* out2 = out1 + B_ * NC_;          // x2 [256,4096]

    dim3 gdec(NDEC / BN, B_ / BM);                     // 128 x 2 = 256 CTAs
    decoder_kernel<<<gdec, 256>>>(x, W1, b1, W2, b2, out2);

    dim3 gfc((NC_ + BN - 1) / BN, B_ / BM, FSPLIT);    // 8 x 2 x 8 = 128 CTAs
    fc_kernel<<<gfc, 256>>>(x, fcW);
    fc_reduce<<<(B_ * NC_ + 255) / 256, 256>>>(fcb, out1);
}

// round 3
// speedup vs baseline: 2.7347x; 1.1454x over previous
#include <cuda_runtime.h>
#include <cstddef>

typedef unsigned long long ull;

__device__ __forceinline__ ull ffma2(ull a, ull b, ull c) {
    ull d;
    asm("fma.rn.f32x2 %0, %1, %2, %3;" : "=l"(d) : "l"(a), "l"(b), "l"(c));
    return d;
}
__device__ __forceinline__ ull splat2(float f) {
    ull d;
    asm("mov.b64 %0, {%1, %1};" : "=l"(d) : "f"(f));
    return d;
}
__device__ __forceinline__ float lo32(ull v) { return __uint_as_float((unsigned)v); }
__device__ __forceinline__ float hi32(ull v) { return __uint_as_float((unsigned)(v >> 32)); }

#define B_    256
#define IN_   2048
#define NC_   1000
#define O_    4096
#define H_    4
#define NDEC  (O_ * H_)   // 16384
#define NEG_SLOPE 0.1f

#define BM 128
#define BN 128
#define BK 16

#define FSPLIT 16
__device__ float fc_scratch[FSPLIT * B_ * NC_];

// Inner product over one smem ktile.
//   As: plain [m][k]  (A read = broadcast LDS.32, splat via MOV)
//   Bs: plain [k][n]  (B read = natural f32x2 pairs, conflict-free LDS.128)
//   acc[r][j]: r = m row (ty*8+r); j: n = tx*4+{0,1},{2,3} / 64+tx*4+{0,1},{2,3}
#define INNER_LOOP(AsT, BsT, acc, tx, ty)                                     \
    _Pragma("unroll")                                                         \
    for (int k = 0; k < BK; k++) {                                            \
        ull a[8];                                                             \
        _Pragma("unroll")                                                     \
        for (int r = 0; r < 8; r++) a[r] = splat2(AsT[ty * 8 + r][k]);        \
        ulonglong2 b0 = *(const ulonglong2*)&BsT[k][tx * 4];                  \
        ulonglong2 b1 = *(const ulonglong2*)&BsT[k][64 + tx * 4];             \
        ull bv[4] = {b0.x, b0.y, b1.x, b1.y};                                 \
        _Pragma("unroll")                                                     \
        for (int r = 0; r < 8; r++) {                                         \
            _Pragma("unroll")                                                 \
            for (int j = 0; j < 4; j++)                                       \
                acc[r][j] = ffma2(a[r], bv[j], acc[r][j]);                    \
        }                                                                     \
    }

// ---------------------------------------------------------------------------
// Decoder: C[256,16384] = X @ W1r, epilogue bias+leaky+collapse -> [256,4096]
// ---------------------------------------------------------------------------
__global__ __launch_bounds__(256, 2)
void decoder_kernel(const float* __restrict__ x, const float* __restrict__ W1,
                    const float* __restrict__ b1, const float* __restrict__ W2,
                    const float* __restrict__ b2, float* __restrict__ out2)
{
    __shared__ float As[2][BM][BK];
    __shared__ float Bs[2][BK][BN];

    const int tid = threadIdx.x;
    const int tx = tid & 15;
    const int ty = tid >> 4;
    const int m0 = blockIdx.y * BM;
    const int n0 = blockIdx.x * BN;

    ull acc[8][4];
    #pragma unroll
    for (int r = 0; r < 8; r++)
        #pragma unroll
        for (int j = 0; j < 4; j++) acc[r][j] = 0ull;

    const int ar = tid >> 2;              // 0..63
    const int ac = (tid & 3) * 4;         // k offset (float4)
    const int o_l = tid & 31;             // decoder within tile
    const int e   = tid >> 5;             // 8-float chunk index
    const float* w1p = W1 + (size_t)(n0 / 4 + o_l) * (IN_ * H_) + e * 8;
    const float* xa0 = x + (size_t)(m0 + ar) * IN_ + ac;
    const float* xa1 = x + (size_t)(m0 + ar + 64) * IN_ + ac;

    const int NT = IN_ / BK;              // 128 ktiles

    // Prologue: tile 0 -> buf 0
    {
        float4 pa0 = *(const float4*)(xa0);
        float4 pa1 = *(const float4*)(xa1);
        float4 pb0 = *(const float4*)(w1p);
        float4 pb1 = *(const float4*)(w1p + 4);
        *(float4*)&As[0][ar][ac]          = pa0;
        *(float4*)&As[0][ar + 64][ac]     = pa1;
        *(float4*)&Bs[0][2 * e][o_l * 4]     = pb0;
        *(float4*)&Bs[0][2 * e + 1][o_l * 4] = pb1;
    }
    __syncthreads();

    for (int kt = 0; kt < NT; kt++) {
        const int buf = kt & 1;
        float4 pa0, pa1, pb0, pb1;
        if (kt + 1 < NT) {
            const int k0 = (kt + 1) * BK;
            pa0 = *(const float4*)(xa0 + k0);
            pa1 = *(const float4*)(xa1 + k0);
            const float* p0 = w1p + (size_t)k0 * H_;
            pb0 = *(const float4*)(p0);
            pb1 = *(const float4*)(p0 + 4);
        }
        INNER_LOOP(As[buf], Bs[buf], acc, tx, ty)
        if (kt + 1 < NT) {
            const int nb = buf ^ 1;
            *(float4*)&As[nb][ar][ac]          = pa0;
            *(float4*)&As[nb][ar + 64][ac]     = pa1;
            *(float4*)&Bs[nb][2 * e][o_l * 4]     = pb0;
            *(float4*)&Bs[nb][2 * e + 1][o_l * 4] = pb1;
        }
        __syncthreads();
    }

    // Epilogue: each thread owns 2 full decoders
    const int gn0 = n0 + tx * 4;
    const int gn1 = gn0 + 64;
    const int d0 = gn0 >> 2, d1 = gn1 >> 2;
    float b1a[4], w2a[4], b1b[4], w2b[4];
    #pragma unroll
    for (int h = 0; h < 4; h++) {
        b1a[h] = b1[gn0 + h]; w2a[h] = W2[gn0 + h];
        b1b[h] = b1[gn1 + h]; w2b[h] = W2[gn1 + h];
    }
    const float b2a = b2[d0], b2b = b2[d1];

    #pragma unroll
    for (int r = 0; r < 8; r++) {
        const int gm = m0 + ty * 8 + r;
        float s0 = 0.f, s1 = 0.f;
        #pragma unroll
        for (int j = 0; j < 2; j++) {
            float va0 = lo32(acc[r][j]) + b1a[2 * j];
            float va1 = hi32(acc[r][j]) + b1a[2 * j + 1];
            va0 = va0 >= 0.f ? va0 : NEG_SLOPE * va0;
            va1 = va1 >= 0.f ? va1 : NEG_SLOPE * va1;
            s0 += va0 * w2a[2 * j] + va1 * w2a[2 * j + 1];
            float vb0 = lo32(acc[r][j + 2]) + b1b[2 * j];
            float vb1 = hi32(acc[r][j + 2]) + b1b[2 * j + 1];
            vb0 = vb0 >= 0.f ? vb0 : NEG_SLOPE * vb0;
            vb1 = vb1 >= 0.f ? vb1 : NEG_SLOPE * vb1;
            s1 += vb0 * w2b[2 * j] + vb1 * w2b[2 * j + 1];
        }
        out2[(size_t)gm * O_ + d0] = s0 + b2a;
        out2[(size_t)gm * O_ + d1] = s1 + b2b;
    }
}

// ---------------------------------------------------------------------------
// fc head: split-K=16 into scratch, then reduce.
// ---------------------------------------------------------------------------
__global__ __launch_bounds__(256, 2)
void fc_kernel(const float* __restrict__ x, const float* __restrict__ fcW)
{
    __shared__ float As[2][BM][BK];
    __shared__ float Bs[2][BK][BN];

    const int tid = threadIdx.x;
    const int tx = tid & 15;
    const int ty = tid >> 4;
    const int m0 = blockIdx.y * BM;
    const int n0 = blockIdx.x * BN;
    const int z  = blockIdx.z;

    ull acc[8][4];
    #pragma unroll
    for (int r = 0; r < 8; r++)
        #pragma unroll
        for (int j = 0; j < 4; j++) acc[r][j] = 0ull;

    const int ar = tid >> 2;
    const int ac = (tid & 3) * 4;
    const int n_l = tid >> 1;             // 0..127
    const int kc  = (tid & 1) * 8;        // k sub-chunk
    const int n_g = n0 + n_l;
    const bool nvalid = (n_g < NC_);
    const int zk = z * (IN_ / FSPLIT);
    const float* xa0 = x + (size_t)(m0 + ar) * IN_ + zk + ac;
    const float* xa1 = x + (size_t)(m0 + ar + 64) * IN_ + zk + ac;
    const float* wp  = fcW + (size_t)n_g * IN_ + zk + kc;

    const int NT = (IN_ / FSPLIT) / BK;   // 8 ktiles

    {
        float4 pa0 = *(const float4*)(xa0);
        float4 pa1 = *(const float4*)(xa1);
        float4 pb0 = make_float4(0.f, 0.f, 0.f, 0.f), pb1 = pb0;
        if (nvalid) { pb0 = *(const float4*)(wp); pb1 = *(const float4*)(wp + 4); }
        *(float4*)&As[0][ar][ac]      = pa0;
        *(float4*)&As[0][ar + 64][ac] = pa1;
        Bs[0][kc + 0][n_l] = pb0.x; Bs[0][kc + 1][n_l] = pb0.y;
        Bs[0][kc + 2][n_l] = pb0.z; Bs[0][kc + 3][n_l] = pb0.w;
        Bs[0][kc + 4][n_l] = pb1.x; Bs[0][kc + 5][n_l] = pb1.y;
        Bs[0][kc + 6][n_l] = pb1.z; Bs[0][kc + 7][n_l] = pb1.w;
    }
    __syncthreads();

    for (int kt = 0; kt < NT; kt++) {
        const int buf = kt & 1;
        float4 pa0, pa1, pb0, pb1;
        if (kt + 1 < NT) {
            const int k0 = (kt + 1) * BK;
            pa0 = *(const float4*)(xa0 + k0);
            pa1 = *(const float4*)(xa1 + k0);
            pb0 = make_float4(0.f, 0.f, 0.f, 0.f); pb1 = pb0;
            if (nvalid) { pb0 = *(const float4*)(wp + k0); pb1 = *(const float4*)(wp + k0 + 4); }
        }
        INNER_LOOP(As[buf], Bs[buf], acc, tx, ty)
        if (kt + 1 < NT) {
            const int nb = buf ^ 1;
            *(float4*)&As[nb][ar][ac]      = pa0;
            *(float4*)&As[nb][ar + 64][ac] = pa1;
            Bs[nb][kc + 0][n_l] = pb0.x; Bs[nb][kc + 1][n_l] = pb0.y;
            Bs[nb][kc + 2][n_l] = pb0.z; Bs[nb][kc + 3][n_l] = pb0.w;
            Bs[nb][kc + 4][n_l] = pb1.x; Bs[nb][kc + 5][n_l] = pb1.y;
            Bs[nb][kc + 6][n_l] = pb1.z; Bs[nb][kc + 7][n_l] = pb1.w;
        }
        __syncthreads();
    }

    float* scr = fc_scratch + (size_t)z * (B_ * NC_);
    const int gn0 = n0 + tx * 4;
    #pragma unroll
    for (int r = 0; r < 8; r++) {
        const int gm = m0 + ty * 8 + r;
        #pragma unroll
        for (int j = 0; j < 4; j++) {
            const int gn = gn0 + (j >> 1) * 64 + (j & 1) * 2;
            float v0 = lo32(acc[r][j]);
            float v1 = hi32(acc[r][j]);
            if (gn < NC_)     scr[(size_t)gm * NC_ + gn]     = v0;
            if (gn + 1 < NC_) scr[(size_t)gm * NC_ + gn + 1] = v1;
        }
    }
}

__global__ void fc_reduce(const float* __restrict__ fcb, float* __restrict__ out1)
{
    const int i = blockIdx.x * blockDim.x + threadIdx.x;
    if (i >= B_ * NC_) return;
    const int c = i % NC_;
    float s = fcb[c];
    #pragma unroll
    for (int z = 0; z < FSPLIT; z++) s += fc_scratch[(size_t)z * (B_ * NC_) + i];
    out1[i] = s;
}

// ---------------------------------------------------------------------------
extern "C" void kernel_launch(void* const* d_in, const int* in_sizes, int n_in,
                              void* d_out, int out_size)
{
    const float* x   = (const float*)d_in[0];
    const float* fcW = (const float*)d_in[1];
    const float* fcb = (const float*)d_in[2];
    const float* W1  = (const float*)d_in[3];
    const float* b1  = (const float*)d_in[4];
    const float* W2  = (const float*)d_in[5];
    const float* b2  = (const float*)d_in[6];

    float* out1 = (float*)d_out;            // x1 [256,1000]
    float* out2 = out1 + B_ * NC_;          // x2 [256,4096]

    dim3 gdec(NDEC / BN, B_ / BM);                     // 128 x 2 = 256 CTAs
    decoder_kernel<<<gdec, 256>>>(x, W1, b1, W2, b2, out2);

    dim3 gfc((NC_ + BN - 1) / BN, B_ / BM, FSPLIT);    // 8 x 2 x 16 = 256 CTAs
    fc_kernel<<<gfc, 256>>>(x, fcW);
    fc_reduce<<<(B_ * NC_ + 255) / 256, 256>>>(fcb, out1);
}